// round 7
// baseline (speedup 1.0000x reference)
#include <cuda_runtime.h>
#include <cstdint>

// Lorenz RK4 over N=8M states. Bulk-copy engine moves all global<->shared
// data; tile pipelined in 5 chunks; L2 evict_first policy on both streams.

#define DT     0.01f
#define SIGMA  10.0f
#define RHO    28.0f
#define BETA   (8.0f / 3.0f)

#define BLOCK_THREADS   128
#define NCHUNK          5
#define CHUNK_STATES    512                       // 512*12 = 6144 B
#define CHUNK_BYTES     (CHUNK_STATES * 12)
#define TILE_STATES     (NCHUNK * CHUNK_STATES)   // 2560  (8M = 3125 * 2560)
#define TILE_BYTES      (TILE_STATES * 12)        // 30720 B
#define THR_BYTES       (CHUNK_BYTES / BLOCK_THREADS)  // 48 B = 4 states

__device__ __forceinline__ uint32_t smem_u32(const void* p) {
    uint32_t a;
    asm("{ .reg .u64 t; cvta.to.shared.u64 t, %1; cvt.u32.u64 %0, t; }"
        : "=r"(a) : "l"(p));
    return a;
}

__device__ __forceinline__ void lorenz_f(float x, float y, float z,
                                         float& dx, float& dy, float& dz) {
    dx = SIGMA * (y - x);
    dy = x * (RHO - z) - y;
    dz = x * y - BETA * z;
}

__device__ __forceinline__ void rk4_step(float& x, float& y, float& z) {
    const float h2 = 0.5f * DT;
    float k1x, k1y, k1z, k2x, k2y, k2z, k3x, k3y, k3z, k4x, k4y, k4z;

    lorenz_f(x, y, z, k1x, k1y, k1z);
    lorenz_f(x + h2 * k1x, y + h2 * k1y, z + h2 * k1z, k2x, k2y, k2z);
    lorenz_f(x + h2 * k2x, y + h2 * k2y, z + h2 * k2z, k3x, k3y, k3z);
    lorenz_f(x + DT * k3x, y + DT * k3y, z + DT * k3z, k4x, k4y, k4z);

    const float w = DT / 6.0f;
    x += w * (k1x + 2.0f * k2x + 2.0f * k3x + k4x);
    y += w * (k1y + 2.0f * k2y + 2.0f * k3y + k4y);
    z += w * (k1z + 2.0f * k2z + 2.0f * k3z + k4z);
}

__global__ void __launch_bounds__(BLOCK_THREADS)
lorenz_rk4_pipe_kernel(const char* __restrict__ gin,
                       char* __restrict__ gout)
{
    __shared__ alignas(128) char tile[TILE_BYTES];       // 30 KB
    __shared__ alignas(8)  uint64_t mbar[NCHUNK];

    const int tid = threadIdx.x;
    const uint32_t s_tile = smem_u32(tile);

    const char* src = gin  + (long long)blockIdx.x * TILE_BYTES;
    char*       dst = gout + (long long)blockIdx.x * TILE_BYTES;

    // streaming eviction policy for both directions
    uint64_t pol;
    asm("createpolicy.fractional.L2::evict_first.b64 %0, 1.0;" : "=l"(pol));

    if (tid == 0) {
        #pragma unroll
        for (int c = 0; c < NCHUNK; c++)
            asm volatile("mbarrier.init.shared.b64 [%0], 1;"
                         :: "r"(smem_u32(&mbar[c])) : "memory");
    }
    __syncthreads();

    // issue all chunk loads up front; engine pipelines them in order
    if (tid == 0) {
        #pragma unroll
        for (int c = 0; c < NCHUNK; c++) {
            uint32_t mb = smem_u32(&mbar[c]);
            asm volatile("mbarrier.arrive.expect_tx.shared.b64 _, [%0], %1;"
                         :: "r"(mb), "r"((uint32_t)CHUNK_BYTES) : "memory");
            asm volatile(
                "cp.async.bulk.shared::cta.global.mbarrier::complete_tx::bytes"
                ".L2::cache_hint [%0], [%1], %2, [%3], %4;"
                :: "r"(s_tile + c * CHUNK_BYTES),
                   "l"(src + c * CHUNK_BYTES),
                   "r"((uint32_t)CHUNK_BYTES),
                   "r"(mb), "l"(pol)
                : "memory");
        }
    }

    #pragma unroll
    for (int c = 0; c < NCHUNK; c++) {
        // wait for this chunk's data (parity 0; each barrier used once)
        {
            const uint32_t mb = smem_u32(&mbar[c]);
            uint32_t done;
            asm volatile(
                "{\n\t.reg .pred p;\n\t"
                "mbarrier.try_wait.parity.acquire.cta.shared::cta.b64 p, [%1], 0;\n\t"
                "selp.b32 %0, 1, 0, p;\n\t}"
                : "=r"(done) : "r"(mb) : "memory");
            if (!done) {
                asm volatile(
                    "{\n\t.reg .pred P1;\n\t"
                    "WL_%=:\n\t"
                    "mbarrier.try_wait.parity.acquire.cta.shared::cta.b64 P1, [%0], 0, 0x989680;\n\t"
                    "@P1 bra.uni WD_%=;\n\t"
                    "bra.uni WL_%=;\n\t"
                    "WD_%=:\n\t}"
                    :: "r"(mb) : "memory");
            }
        }

        // compute: 4 consecutive states (48 B) per thread within the chunk
        float4* my = (float4*)(tile + c * CHUNK_BYTES + tid * THR_BYTES);
        float4 a = my[0];
        float4 b = my[1];
        float4 d = my[2];
        float s[12] = { a.x, a.y, a.z, a.w,
                        b.x, b.y, b.z, b.w,
                        d.x, d.y, d.z, d.w };
        #pragma unroll
        for (int i = 0; i < 4; i++)
            rk4_step(s[3*i + 0], s[3*i + 1], s[3*i + 2]);
        my[0] = make_float4(s[0], s[1], s[2],  s[3]);
        my[1] = make_float4(s[4], s[5], s[6],  s[7]);
        my[2] = make_float4(s[8], s[9], s[10], s[11]);

        __syncthreads();

        // eager per-chunk store; overlaps with compute of next chunk
        if (tid == 0) {
            asm volatile("fence.proxy.async.shared::cta;" ::: "memory");
            asm volatile(
                "cp.async.bulk.global.shared::cta.bulk_group.L2::cache_hint "
                "[%0], [%1], %2, %3;"
                :: "l"(dst + c * CHUNK_BYTES),
                   "r"(s_tile + c * CHUNK_BYTES),
                   "r"((uint32_t)CHUNK_BYTES), "l"(pol)
                : "memory");
            asm volatile("cp.async.bulk.commit_group;" ::: "memory");
        }
    }

    // keep CTA alive until engine has read all smem
    if (tid == 0)
        asm volatile("cp.async.bulk.wait_group 0;" ::: "memory");
}

// Scalar tail (unused for N=8M: 3125 * 2560 == 8,000,000 exactly).
__global__ void
lorenz_rk4_tail_kernel(const float* __restrict__ in,
                       float* __restrict__ out,
                       int start, int n_states)
{
    int i = start + blockIdx.x * blockDim.x + threadIdx.x;
    if (i >= n_states) return;
    float x = in[3*i + 0];
    float y = in[3*i + 1];
    float z = in[3*i + 2];
    rk4_step(x, y, z);
    out[3*i + 0] = x;
    out[3*i + 1] = y;
    out[3*i + 2] = z;
}

extern "C" void kernel_launch(void* const* d_in, const int* in_sizes, int n_in,
                              void* d_out, int out_size)
{
    const float* in = (const float*)d_in[0];
    float* out = (float*)d_out;
    int n_states = in_sizes[0] / 3;                 // 8,000,000

    int n_blocks = n_states / TILE_STATES;          // 3125 for 8M
    if (n_blocks > 0)
        lorenz_rk4_pipe_kernel<<<n_blocks, BLOCK_THREADS>>>(
            (const char*)in, (char*)out);

    int done = n_blocks * TILE_STATES;
    int tail = n_states - done;                     // 0 for 8M
    if (tail > 0) {
        int block = 256;
        int grid = (tail + block - 1) / block;
        lorenz_rk4_tail_kernel<<<grid, block>>>(in, out, done, n_states);
    }
}